// round 1
// baseline (speedup 1.0000x reference)
#include <cuda_runtime.h>
#include <math.h>
#include <float.h>

// Problem constants
#define B_   8
#define L_   2048
#define LOG2L 11
#define D_   512
#define DM_  512
#define KTOP 15

// ---------------- device scratch (static allocation only) ----------------
__device__ float g_qT[B_ * D_ * L_];   // (B, D, L)
__device__ float g_kT[B_ * D_ * L_];
__device__ float g_vT[B_ * D_ * L_];
__device__ float g_AT[B_ * D_ * L_];
__device__ float2 g_tw[L_ / 2];        // exp(-2*pi*i*j/L), j=0..1023

// ---------------- twiddle init ----------------
__global__ void twiddle_init_kernel() {
    int j = blockIdx.x * blockDim.x + threadIdx.x;
    if (j < L_ / 2) {
        float sn, cs;
        // angle = 2*pi*j/L = pi * (j/1024)
        sincospif((float)j / 1024.0f, &sn, &cs);
        g_tw[j] = make_float2(cs, -sn);
    }
}

// ---------------- GEMM: out^T[b,d,t] = (X @ W + bias)  ----------------
// X: (B*L, DM) row-major. W: (DM, D) row-major. Writes transposed (B, D, L).
// Block tile 128(t) x 128(d), K-tile 8, 256 threads, 8x8 microtile.
__global__ __launch_bounds__(256, 2)
void gemm_bias_t_kernel(const float* __restrict__ X,
                        const float* __restrict__ W,
                        const float* __restrict__ bias,
                        int which) {
    float* outT = (which == 0) ? g_qT : ((which == 1) ? g_kT : g_vT);

    __shared__ float As[8][132];   // k-major, t along 132-stride rows (528B, 16B aligned)
    __shared__ float Bs[8][128];   // k-major, d along rows

    const int tid = threadIdx.x;
    const int tx = tid & 15;    // t group (8 consecutive t each)
    const int ty = tid >> 4;    // d group (8 consecutive d each)
    const int m0 = blockIdx.x * 128;
    const int n0 = blockIdx.y * 128;

    const int arow = tid >> 1;         // 0..127
    const int acol = (tid & 1) * 4;    // 0 or 4
    const int brow = tid >> 5;         // 0..7
    const int bcol = (tid & 31) * 4;   // 0..124

    float c[8][8];
#pragma unroll
    for (int i = 0; i < 8; i++)
#pragma unroll
        for (int j = 0; j < 8; j++) c[i][j] = 0.0f;

    for (int k0 = 0; k0 < DM_; k0 += 8) {
        float4 av = *(const float4*)&X[(size_t)(m0 + arow) * DM_ + k0 + acol];
        float4 bv = *(const float4*)&W[(size_t)(k0 + brow) * D_ + n0 + bcol];
        __syncthreads();
        As[acol + 0][arow] = av.x;
        As[acol + 1][arow] = av.y;
        As[acol + 2][arow] = av.z;
        As[acol + 3][arow] = av.w;
        *(float4*)&Bs[brow][bcol] = bv;
        __syncthreads();
#pragma unroll
        for (int kk = 0; kk < 8; kk++) {
            float4 a0 = *(const float4*)&As[kk][tx * 8];
            float4 a1 = *(const float4*)&As[kk][tx * 8 + 4];
            float4 b0 = *(const float4*)&Bs[kk][ty * 8];
            float4 b1 = *(const float4*)&Bs[kk][ty * 8 + 4];
            float a[8] = {a0.x, a0.y, a0.z, a0.w, a1.x, a1.y, a1.z, a1.w};
            float b[8] = {b0.x, b0.y, b0.z, b0.w, b1.x, b1.y, b1.z, b1.w};
#pragma unroll
            for (int i = 0; i < 8; i++)
#pragma unroll
                for (int j = 0; j < 8; j++) c[i][j] = fmaf(a[i], b[j], c[i][j]);
        }
    }

    // epilogue: bias add + transposed store (coalesced along t)
    const int b = m0 >> LOG2L;              // tile never crosses batch (2048 % 128 == 0)
    const int t0 = (m0 & (L_ - 1)) + tx * 8;
#pragma unroll
    for (int j = 0; j < 8; j++) {
        const int d = n0 + ty * 8 + j;
        const float bi = bias[d];
        float4 o0 = make_float4(c[0][j] + bi, c[1][j] + bi, c[2][j] + bi, c[3][j] + bi);
        float4 o1 = make_float4(c[4][j] + bi, c[5][j] + bi, c[6][j] + bi, c[7][j] + bi);
        size_t base = ((size_t)(b * D_ + d) << LOG2L) + t0;
        *(float4*)&outT[base] = o0;
        *(float4*)&outT[base + 4] = o1;
    }
}

// ---------------- complex helpers ----------------
__device__ __forceinline__ float2 cmul(float2 a, float2 b) {
    return make_float2(a.x * b.x - a.y * b.y, a.x * b.y + a.y * b.x);
}

// ---------------- fused FFT-correlation + top-k + softmax + gather ----------------
// One CTA per (b, d). 256 threads.
__global__ __launch_bounds__(256)
void corr_attn_kernel() {
    __shared__ float2 tw[L_ / 2];     // 8 KB
    __shared__ float2 z[L_];          // 16 KB (also reused as v column, first 8KB)
    __shared__ float2 s[L_];          // 16 KB
    __shared__ float  red_v[256];
    __shared__ int    red_i[256];
    __shared__ float  wsel[KTOP];
    __shared__ int    isel[KTOP];
    __shared__ float  wnorm[KTOP];

    const int tid = threadIdx.x;
    const int bd = blockIdx.x;                 // b*D + d
    const size_t col = (size_t)bd << LOG2L;

    // load twiddles + packed input z = q + i*k
    for (int i = tid; i < L_ / 2; i += 256) tw[i] = g_tw[i];
    for (int i = tid; i < L_; i += 256) z[i] = make_float2(g_qT[col + i], g_kT[col + i]);
    __syncthreads();

    // ---- forward DIF FFT (natural in -> bit-reversed out) ----
#pragma unroll 1
    for (int ls = 10; ls >= 0; ls--) {
        const int span = 1 << ls;
#pragma unroll
        for (int r = 0; r < 4; r++) {
            int bf = tid + r * 256;
            int j = bf & (span - 1);
            int g = bf >> ls;
            int i0 = (g << (ls + 1)) | j;
            int i1 = i0 + span;
            float2 a = z[i0], b = z[i1];
            float2 sum = make_float2(a.x + b.x, a.y + b.y);
            float2 dif = make_float2(a.x - b.x, a.y - b.y);
            float2 w = tw[j << (10 - ls)];
            z[i0] = sum;
            z[i1] = cmul(dif, w);
        }
        __syncthreads();
    }

    // ---- cross-spectrum in bit-reversed domain ----
    // S[f] = Q[f]*conj(K[f]) = (i/4)*(Z[f]+conj(Z[-f]))*(conj(Z[f])-Z[-f]); fold 1/L.
    const float scl = 0.25f / (float)L_;
    for (int p = tid; p < L_; p += 256) {
        int f = __brev((unsigned)p) >> 21;
        int fm = (L_ - f) & (L_ - 1);
        int pm = __brev((unsigned)fm) >> 21;
        float2 Zf = z[p], Zm = z[pm];
        float2 u = make_float2(Zf.x + Zm.x, Zf.y - Zm.y);      // Zf + conj(Zm)
        float2 v = make_float2(Zf.x - Zm.x, -Zf.y - Zm.y);     // conj(Zf) - Zm
        float2 pr = cmul(u, v);
        s[p] = make_float2(-pr.y * scl, pr.x * scl);           // *(i) * scl
    }
    __syncthreads();

    // ---- inverse DIT FFT (bit-reversed in -> natural out), conj twiddles ----
#pragma unroll 1
    for (int ls = 0; ls <= 10; ls++) {
        const int span = 1 << ls;
#pragma unroll
        for (int r = 0; r < 4; r++) {
            int bf = tid + r * 256;
            int j = bf & (span - 1);
            int g = bf >> ls;
            int i0 = (g << (ls + 1)) | j;
            int i1 = i0 + span;
            float2 w = tw[j << (10 - ls)];
            float2 b = s[i1];
            float2 bw = make_float2(b.x * w.x + b.y * w.y, b.y * w.x - b.x * w.y); // b*conj(w)
            float2 a = s[i0];
            s[i0] = make_float2(a.x + bw.x, a.y + bw.y);
            s[i1] = make_float2(a.x - bw.x, a.y - bw.y);
        }
        __syncthreads();
    }
    // now s[tau].x = R[tau] = sum_t q[t]*k[(t-tau) mod L]

    // ---- top-15 via 15 rounds of block argmax ----
    for (int r = 0; r < KTOP; r++) {
        float best = -FLT_MAX;
        int bi = L_;
#pragma unroll
        for (int q8 = 0; q8 < 8; q8++) {
            int p = tid + q8 * 256;
            float vv = s[p].x;
            if (vv > best) { best = vv; bi = p; }
        }
        red_v[tid] = best;
        red_i[tid] = bi;
        __syncthreads();
        for (int off = 128; off > 0; off >>= 1) {
            if (tid < off) {
                float ov = red_v[tid + off];
                int oi = red_i[tid + off];
                if (ov > red_v[tid] || (ov == red_v[tid] && oi < red_i[tid])) {
                    red_v[tid] = ov; red_i[tid] = oi;
                }
            }
            __syncthreads();
        }
        if (tid == 0) {
            wsel[r] = red_v[0];
            isel[r] = red_i[0];
            s[red_i[0]].x = -FLT_MAX;   // exclude from next rounds
        }
        __syncthreads();
    }

    // ---- softmax over the 15 selected ----
    if (tid == 0) {
        float m = wsel[0];
#pragma unroll
        for (int k = 1; k < KTOP; k++) m = fmaxf(m, wsel[k]);
        float sum = 0.0f;
#pragma unroll
        for (int k = 0; k < KTOP; k++) { float e = __expf(wsel[k] - m); wnorm[k] = e; sum += e; }
        float inv = 1.0f / sum;
#pragma unroll
        for (int k = 0; k < KTOP; k++) wnorm[k] *= inv;
    }

    // ---- load v column (reuse z buffer) ----
    float* vcol = (float*)z;
    for (int i = tid; i < L_; i += 256) vcol[i] = g_vT[col + i];
    __syncthreads();

    // ---- gather: A^T[b,d,l] = sum_k w[k] * v[(l + lag_k) mod L] ----
    for (int l = tid; l < L_; l += 256) {
        float acc = 0.0f;
#pragma unroll
        for (int k = 0; k < KTOP; k++)
            acc = fmaf(wnorm[k], vcol[(l + isel[k]) & (L_ - 1)], acc);
        g_AT[col + l] = acc;
    }
}

// ---------------- transpose (B, D, L) -> (B, L, D) ----------------
__global__ void transpose_kernel(float* __restrict__ A) {
    __shared__ float tile[32][33];
    const int b = blockIdx.z;
    const int l0 = blockIdx.x * 32;
    const int d0 = blockIdx.y * 32;
    const int tx = threadIdx.x, ty = threadIdx.y;
#pragma unroll
    for (int r = 0; r < 32; r += 8)
        tile[ty + r][tx] = g_AT[((size_t)(b * D_ + d0 + ty + r) << LOG2L) + l0 + tx];
    __syncthreads();
#pragma unroll
    for (int r = 0; r < 32; r += 8)
        A[((size_t)(b * L_ + l0 + ty + r)) * D_ + d0 + tx] = tile[tx][ty + r];
}

// ---------------- launch ----------------
extern "C" void kernel_launch(void* const* d_in, const int* in_sizes, int n_in,
                              void* d_out, int out_size) {
    const float* Q   = (const float*)d_in[0];
    const float* K   = (const float*)d_in[1];
    const float* V   = (const float*)d_in[2];
    const float* WQw = (const float*)d_in[3];
    const float* WQb = (const float*)d_in[4];
    const float* WKw = (const float*)d_in[5];
    const float* WKb = (const float*)d_in[6];
    const float* WVw = (const float*)d_in[7];
    const float* WVb = (const float*)d_in[8];
    float* out = (float*)d_out;

    twiddle_init_kernel<<<4, 256>>>();

    dim3 ggrid(B_ * L_ / 128, D_ / 128);   // (128, 4)
    gemm_bias_t_kernel<<<ggrid, 256>>>(Q, WQw, WQb, 0);
    gemm_bias_t_kernel<<<ggrid, 256>>>(K, WKw, WKb, 1);
    gemm_bias_t_kernel<<<ggrid, 256>>>(V, WVw, WVb, 2);

    corr_attn_kernel<<<B_ * D_, 256>>>();

    dim3 tgrid(L_ / 32, D_ / 32, B_);      // (64, 16, 8)
    transpose_kernel<<<tgrid, dim3(32, 8)>>>(out);
}

// round 3
// speedup vs baseline: 1.0579x; 1.0579x over previous
#include <cuda_runtime.h>
#include <math.h>
#include <float.h>

// Problem constants
#define B_   8
#define L_   2048
#define LOG2L 11
#define D_   512
#define DM_  512
#define KTOP 15

// ---------------- device scratch (static allocation only) ----------------
__device__ float g_qT[B_ * D_ * L_];   // (B, D, L)
__device__ float g_kT[B_ * D_ * L_];
__device__ float g_vT[B_ * D_ * L_];
__device__ float g_AT[B_ * D_ * L_];
__device__ float2 g_tw[L_ / 2];        // exp(-2*pi*i*j/L)

// ---------------- twiddle init ----------------
__global__ void twiddle_init_kernel() {
    int j = blockIdx.x * blockDim.x + threadIdx.x;
    if (j < L_ / 2) {
        float sn, cs;
        sincospif((float)j / 1024.0f, &sn, &cs);
        g_tw[j] = make_float2(cs, -sn);
    }
}

// ---------------- TF32 helpers ----------------
__device__ __forceinline__ unsigned f2tf32(float x) {
    unsigned u;
    asm("cvt.rna.tf32.f32 %0, %1;" : "=r"(u) : "f"(x));
    return u;
}

// split x = hi + lo, both exactly representable in tf32
__device__ __forceinline__ void tf32_split(float x, unsigned& hi, unsigned& lo) {
    hi = f2tf32(x);
    float r = x - __uint_as_float(hi);
    lo = f2tf32(r);
}

__device__ __forceinline__ void mma_tf32(float c[4], const unsigned a[4], const unsigned b[2]) {
    asm volatile(
        "mma.sync.aligned.m16n8k8.row.col.f32.tf32.tf32.f32 "
        "{%0,%1,%2,%3}, {%4,%5,%6,%7}, {%8,%9}, {%0,%1,%2,%3};\n"
        : "+f"(c[0]), "+f"(c[1]), "+f"(c[2]), "+f"(c[3])
        : "r"(a[0]), "r"(a[1]), "r"(a[2]), "r"(a[3]), "r"(b[0]), "r"(b[1]));
}

// ---------------- GEMM (3xTF32 tensor core, ~fp32 accuracy) ----------------
// out^T[b,d,t] = X @ W + bias. X: (B*L, DM) row-major. W: (DM, D) row-major.
// Writes transposed (B, D, L). CTA tile 128(t) x 128(d), K-tile 32;
// 8 warps as 2(m) x 4(n); warp tile 64x32.
__global__ __launch_bounds__(256)
void gemm_tf32_t_kernel(const float* __restrict__ X,
                        const float* __restrict__ W,
                        const float* __restrict__ bias,
                        int which) {
    float* outT = (which == 0) ? g_qT : ((which == 1) ? g_kT : g_vT);

    __shared__ float As[128][36];   // [t][k]  (bank-conflict-free frag loads)
    __shared__ float Bs[32][136];   // [k][n]

    const int tid = threadIdx.x;
    const int lane = tid & 31;
    const int w = tid >> 5;
    const int wm0 = (w & 1) * 64;
    const int wn0 = (w >> 1) * 32;
    const int r = lane >> 2;    // 0..7
    const int c = lane & 3;     // 0..3
    const int m0 = blockIdx.x * 128;
    const int n0 = blockIdx.y * 128;

    float cacc[4][4][4];
#pragma unroll
    for (int mt = 0; mt < 4; mt++)
#pragma unroll
        for (int nt = 0; nt < 4; nt++)
#pragma unroll
            for (int i = 0; i < 4; i++) cacc[mt][nt][i] = 0.0f;

    for (int k0 = 0; k0 < DM_; k0 += 32) {
        __syncthreads();
        // load A tile 128x32 (coalesced float4 along k)
#pragma unroll
        for (int i = 0; i < 4; i++) {
            int f = tid + i * 256;
            int t = f >> 3;
            int kq = (f & 7) << 2;
            *(float4*)&As[t][kq] = *(const float4*)&X[(size_t)(m0 + t) * DM_ + k0 + kq];
        }
        // load B tile 32x128 (coalesced float4 along n)
#pragma unroll
        for (int i = 0; i < 4; i++) {
            int f = tid + i * 256;
            int k = f >> 5;
            int nq = (f & 31) << 2;
            *(float4*)&Bs[k][nq] = *(const float4*)&W[(size_t)(k0 + k) * D_ + n0 + nq];
        }
        __syncthreads();

#pragma unroll
        for (int ks = 0; ks < 4; ks++) {
            const int kb = ks * 8;
            unsigned ah[4][4], al[4][4], bh[4][2], bl[4][2];
#pragma unroll
            for (int mt = 0; mt < 4; mt++) {
                int row = wm0 + mt * 16 + r;
                tf32_split(As[row][kb + c],         ah[mt][0], al[mt][0]);
                tf32_split(As[row + 8][kb + c],     ah[mt][1], al[mt][1]);
                tf32_split(As[row][kb + c + 4],     ah[mt][2], al[mt][2]);
                tf32_split(As[row + 8][kb + c + 4], ah[mt][3], al[mt][3]);
            }
#pragma unroll
            for (int nt = 0; nt < 4; nt++) {
                int cn = wn0 + nt * 8 + r;
                tf32_split(Bs[kb + c][cn],     bh[nt][0], bl[nt][0]);
                tf32_split(Bs[kb + c + 4][cn], bh[nt][1], bl[nt][1]);
            }
            // 3xTF32: hi*lo + lo*hi first, hi*hi last
#pragma unroll
            for (int mt = 0; mt < 4; mt++)
#pragma unroll
                for (int nt = 0; nt < 4; nt++) {
                    mma_tf32(cacc[mt][nt], ah[mt], bl[nt]);
                    mma_tf32(cacc[mt][nt], al[mt], bh[nt]);
                    mma_tf32(cacc[mt][nt], ah[mt], bh[nt]);
                }
        }
    }

    // epilogue: bias + transposed store (coalesced 32B sectors along t)
    const int b = m0 >> LOG2L;                 // 128 | 2048, tile never crosses batch
    const int tbase = (m0 & (L_ - 1)) + wm0 + r;
#pragma unroll
    for (int nt = 0; nt < 4; nt++) {
        const int d0 = n0 + wn0 + nt * 8 + 2 * c;
        const float bi0 = bias[d0];
        const float bi1 = bias[d0 + 1];
        const size_t row0 = ((size_t)(b * D_ + d0) << LOG2L);
        const size_t row1 = row0 + L_;
#pragma unroll
        for (int mt = 0; mt < 4; mt++) {
            const int t = tbase + mt * 16;
            outT[row0 + t]     = cacc[mt][nt][0] + bi0;
            outT[row1 + t]     = cacc[mt][nt][1] + bi1;
            outT[row0 + t + 8] = cacc[mt][nt][2] + bi0;
            outT[row1 + t + 8] = cacc[mt][nt][3] + bi1;
        }
    }
}

// ---------------- complex helpers ----------------
__device__ __forceinline__ float2 cmul(float2 a, float2 b) {
    return make_float2(a.x * b.x - a.y * b.y, a.x * b.y + a.y * b.x);
}

// ---------------- fused FFT-correlation + top-k + softmax + gather ----------------
// One CTA per (b, d). 256 threads.
__global__ __launch_bounds__(256)
void corr_attn_kernel() {
    __shared__ float2 tw[L_ / 2];     // 8 KB
    __shared__ float2 z[L_];          // 16 KB (reused as v column)
    __shared__ float2 s[L_];          // 16 KB
    __shared__ float  red_v[16];      // per-warp winners, double-buffered per round
    __shared__ int    red_i[16];

    const int tid = threadIdx.x;
    const int lane = tid & 31;
    const int warp = tid >> 5;
    const int bd = blockIdx.x;                 // b*D + d
    const size_t col = (size_t)bd << LOG2L;

    for (int i = tid; i < L_ / 2; i += 256) tw[i] = g_tw[i];
    for (int i = tid; i < L_; i += 256) z[i] = make_float2(g_qT[col + i], g_kT[col + i]);
    __syncthreads();

    // ---- forward DIF FFT (natural -> bit-reversed) ----
#pragma unroll 1
    for (int ls = 10; ls >= 0; ls--) {
        const int span = 1 << ls;
#pragma unroll
        for (int rr = 0; rr < 4; rr++) {
            int bf = tid + rr * 256;
            int j = bf & (span - 1);
            int g = bf >> ls;
            int i0 = (g << (ls + 1)) | j;
            int i1 = i0 + span;
            float2 a = z[i0], b = z[i1];
            float2 sum = make_float2(a.x + b.x, a.y + b.y);
            float2 dif = make_float2(a.x - b.x, a.y - b.y);
            float2 wv = tw[j << (10 - ls)];
            z[i0] = sum;
            z[i1] = cmul(dif, wv);
        }
        __syncthreads();
    }

    // ---- cross-spectrum in bit-reversed domain ----
    const float scl = 0.25f / (float)L_;
    for (int p = tid; p < L_; p += 256) {
        int f = __brev((unsigned)p) >> 21;
        int fm = (L_ - f) & (L_ - 1);
        int pm = __brev((unsigned)fm) >> 21;
        float2 Zf = z[p], Zm = z[pm];
        float2 u = make_float2(Zf.x + Zm.x, Zf.y - Zm.y);
        float2 v = make_float2(Zf.x - Zm.x, -Zf.y - Zm.y);
        float2 pr = cmul(u, v);
        s[p] = make_float2(-pr.y * scl, pr.x * scl);
    }
    __syncthreads();

    // ---- inverse DIT FFT (bit-reversed -> natural), conj twiddles ----
#pragma unroll 1
    for (int ls = 0; ls <= 10; ls++) {
        const int span = 1 << ls;
#pragma unroll
        for (int rr = 0; rr < 4; rr++) {
            int bf = tid + rr * 256;
            int j = bf & (span - 1);
            int g = bf >> ls;
            int i0 = (g << (ls + 1)) | j;
            int i1 = i0 + span;
            float2 wv = tw[j << (10 - ls)];
            float2 b = s[i1];
            float2 bw = make_float2(b.x * wv.x + b.y * wv.y, b.y * wv.x - b.x * wv.y);
            float2 a = s[i0];
            s[i0] = make_float2(a.x + bw.x, a.y + bw.y);
            s[i1] = make_float2(a.x - bw.x, a.y - bw.y);
        }
        __syncthreads();
    }
    // s[tau].x = R[tau]

    // ---- top-15: register-resident values + warp shuffle reduce ----
    float rv[8];
#pragma unroll
    for (int q = 0; q < 8; q++) rv[q] = s[tid + q * 256].x;

    float wsel[KTOP];
    int isel[KTOP];
#pragma unroll 1
    for (int rnd = 0; rnd < KTOP; rnd++) {
        float best = rv[0];
        int bq = 0;
#pragma unroll
        for (int q = 1; q < 8; q++)
            if (rv[q] > best) { best = rv[q]; bq = q; }
        int bi = tid + bq * 256;
#pragma unroll
        for (int off = 16; off > 0; off >>= 1) {
            float ov = __shfl_xor_sync(0xffffffffu, best, off);
            int oi = __shfl_xor_sync(0xffffffffu, bi, off);
            if (ov > best || (ov == best && oi < bi)) { best = ov; bi = oi; }
        }
        const int slot = (rnd & 1) * 8;
        if (lane == 0) { red_v[slot + warp] = best; red_i[slot + warp] = bi; }
        __syncthreads();
        float gb = red_v[slot];
        int gi = red_i[slot];
#pragma unroll
        for (int ww = 1; ww < 8; ww++) {
            float ov = red_v[slot + ww];
            int oi = red_i[slot + ww];
            if (ov > gb || (ov == gb && oi < gi)) { gb = ov; gi = oi; }
        }
        wsel[rnd] = gb;
        isel[rnd] = gi;
        if ((gi & 255) == tid) rv[gi >> 8] = -FLT_MAX;   // exclude (register-local)
    }

    // ---- softmax over the 15 selected (computed redundantly per thread) ----
    float m = wsel[0];
#pragma unroll
    for (int k = 1; k < KTOP; k++) m = fmaxf(m, wsel[k]);
    float sum = 0.0f;
    float wnorm[KTOP];
#pragma unroll
    for (int k = 0; k < KTOP; k++) { float e = __expf(wsel[k] - m); wnorm[k] = e; sum += e; }
    const float inv = 1.0f / sum;
#pragma unroll
    for (int k = 0; k < KTOP; k++) wnorm[k] *= inv;

    // ---- load v column (reuse z buffer) ----
    float* vcol = (float*)z;
    __syncthreads();
    for (int i = tid; i < L_; i += 256) vcol[i] = g_vT[col + i];
    __syncthreads();

    // ---- gather: A^T[b,d,l] = sum_k w[k] * v[(l + lag_k) mod L] ----
    for (int l = tid; l < L_; l += 256) {
        float acc = 0.0f;
#pragma unroll
        for (int k = 0; k < KTOP; k++)
            acc = fmaf(wnorm[k], vcol[(l + isel[k]) & (L_ - 1)], acc);
        g_AT[col + l] = acc;
    }
}

// ---------------- transpose (B, D, L) -> (B, L, D) ----------------
__global__ void transpose_kernel(float* __restrict__ A) {
    __shared__ float tile[32][33];
    const int b = blockIdx.z;
    const int l0 = blockIdx.x * 32;
    const int d0 = blockIdx.y * 32;
    const int tx = threadIdx.x, ty = threadIdx.y;
#pragma unroll
    for (int r = 0; r < 32; r += 8)
        tile[ty + r][tx] = g_AT[((size_t)(b * D_ + d0 + ty + r) << LOG2L) + l0 + tx];
    __syncthreads();
#pragma unroll
    for (int r = 0; r < 32; r += 8)
        A[((size_t)(b * L_ + l0 + ty + r)) * D_ + d0 + tx] = tile[tx][ty + r];
}

// ---------------- launch ----------------
extern "C" void kernel_launch(void* const* d_in, const int* in_sizes, int n_in,
                              void* d_out, int out_size) {
    const float* Q   = (const float*)d_in[0];
    const float* K   = (const float*)d_in[1];
    const float* V   = (const float*)d_in[2];
    const float* WQw = (const float*)d_in[3];
    const float* WQb = (const float*)d_in[4];
    const float* WKw = (const float*)d_in[5];
    const float* WKb = (const float*)d_in[6];
    const float* WVw = (const float*)d_in[7];
    const float* WVb = (const float*)d_in[8];
    float* out = (float*)d_out;

    twiddle_init_kernel<<<4, 256>>>();

    dim3 ggrid(B_ * L_ / 128, D_ / 128);   // (128, 4)
    gemm_tf32_t_kernel<<<ggrid, 256>>>(Q, WQw, WQb, 0);
    gemm_tf32_t_kernel<<<ggrid, 256>>>(K, WKw, WKb, 1);
    gemm_tf32_t_kernel<<<ggrid, 256>>>(V, WVw, WVb, 2);

    corr_attn_kernel<<<B_ * D_, 256>>>();

    dim3 tgrid(L_ / 32, D_ / 32, B_);      // (64, 16, 8)
    transpose_kernel<<<tgrid, dim3(32, 8)>>>(out);
}

// round 4
// speedup vs baseline: 1.3288x; 1.2561x over previous
#include <cuda_runtime.h>
#include <math.h>
#include <float.h>

// Problem constants
#define B_   8
#define L_   2048
#define LOG2L 11
#define D_   512
#define DM_  512
#define KTOP 15

// ---------------- device scratch (static allocation only) ----------------
__device__ float g_qT[B_ * D_ * L_];   // (B, D, L)
__device__ float g_kT[B_ * D_ * L_];
__device__ float g_vT[B_ * D_ * L_];
__device__ float g_AT[B_ * D_ * L_];
__device__ float2 g_tw[L_ / 2];        // exp(-2*pi*i*j/L)

// ---------------- twiddle init ----------------
__global__ void twiddle_init_kernel() {
    int j = blockIdx.x * blockDim.x + threadIdx.x;
    if (j < L_ / 2) {
        float sn, cs;
        sincospif((float)j / 1024.0f, &sn, &cs);
        g_tw[j] = make_float2(cs, -sn);
    }
}

// ---------------- TF32 helpers ----------------
__device__ __forceinline__ float f2tf32f(float x) {
    unsigned u;
    asm("cvt.rna.tf32.f32 %0, %1;" : "=r"(u) : "f"(x));
    return __uint_as_float(u);
}

__device__ __forceinline__ void split4(float4 v, float4& h, float4& l) {
    h.x = f2tf32f(v.x); l.x = f2tf32f(v.x - h.x);
    h.y = f2tf32f(v.y); l.y = f2tf32f(v.y - h.y);
    h.z = f2tf32f(v.z); l.z = f2tf32f(v.z - h.z);
    h.w = f2tf32f(v.w); l.w = f2tf32f(v.w - h.w);
}

__device__ __forceinline__ void mma_tf32(float c[4], const unsigned a[4], const unsigned b[2]) {
    asm volatile(
        "mma.sync.aligned.m16n8k8.row.col.f32.tf32.tf32.f32 "
        "{%0,%1,%2,%3}, {%4,%5,%6,%7}, {%8,%9}, {%0,%1,%2,%3};\n"
        : "+f"(c[0]), "+f"(c[1]), "+f"(c[2]), "+f"(c[3])
        : "r"(a[0]), "r"(a[1]), "r"(a[2]), "r"(a[3]), "r"(b[0]), "r"(b[1]));
}

// ---------------- Fused 3-GEMM (3xTF32, hi/lo pre-split in smem) ----------------
// out^T[b,d,t] = X @ W + bias, for (X,W,bias,out) selected by blockIdx.z.
// CTA tile 128(t) x 128(d), K-tile 16; 8 warps as 2(m) x 4(n); warp tile 64x32.
__global__ __launch_bounds__(256, 2)
void gemm3_tf32_kernel(const float* __restrict__ Qi, const float* __restrict__ Ki,
                       const float* __restrict__ Vi,
                       const float* __restrict__ WQ, const float* __restrict__ WK,
                       const float* __restrict__ WV,
                       const float* __restrict__ bQ, const float* __restrict__ bK,
                       const float* __restrict__ bV) {
    const int z = blockIdx.z;
    const float* X    = (z == 0) ? Qi : ((z == 1) ? Ki : Vi);
    const float* W    = (z == 0) ? WQ : ((z == 1) ? WK : WV);
    const float* bias = (z == 0) ? bQ : ((z == 1) ? bK : bV);
    float* outT       = (z == 0) ? g_qT : ((z == 1) ? g_kT : g_vT);

    __shared__ float Ah[128][20], Al[128][20];   // [t][k], stride 20: conflict-free frags
    __shared__ float Bh[16][136], Bl[16][136];   // [k][n], stride 136: conflict-free frags

    const int tid = threadIdx.x;
    const int lane = tid & 31;
    const int w = tid >> 5;
    const int wm0 = (w & 1) * 64;
    const int wn0 = (w >> 1) * 32;
    const int r = lane >> 2;    // 0..7
    const int c = lane & 3;     // 0..3
    const int m0 = blockIdx.x * 128;
    const int n0 = blockIdx.y * 128;

    // load index precompute (A: 2 float4/thread, B: 2 float4/thread per k-tile)
    const int tA0 = tid >> 2,            kqA0 = (tid & 3) << 2;
    const int tA1 = (tid + 256) >> 2,    kqA1 = ((tid + 256) & 3) << 2;
    const int kB0 = tid >> 5,            nqB0 = (tid & 31) << 2;
    const int kB1 = (tid + 256) >> 5,    nqB1 = ((tid + 256) & 31) << 2;
    const float* pA0 = &X[(size_t)(m0 + tA0) * DM_ + kqA0];
    const float* pA1 = &X[(size_t)(m0 + tA1) * DM_ + kqA1];
    const float* pB0 = &W[(size_t)kB0 * D_ + n0 + nqB0];
    const float* pB1 = &W[(size_t)kB1 * D_ + n0 + nqB1];

    float cacc[4][4][4];
#pragma unroll
    for (int mt = 0; mt < 4; mt++)
#pragma unroll
        for (int nt = 0; nt < 4; nt++)
#pragma unroll
            for (int i = 0; i < 4; i++) cacc[mt][nt][i] = 0.0f;

    float4 av0 = *(const float4*)pA0;
    float4 av1 = *(const float4*)pA1;
    float4 bv0 = *(const float4*)pB0;
    float4 bv1 = *(const float4*)pB1;

#pragma unroll 1
    for (int k0 = 0; k0 < DM_; k0 += 16) {
        // split + store current tile
        float4 h, l;
        split4(av0, h, l); *(float4*)&Ah[tA0][kqA0] = h; *(float4*)&Al[tA0][kqA0] = l;
        split4(av1, h, l); *(float4*)&Ah[tA1][kqA1] = h; *(float4*)&Al[tA1][kqA1] = l;
        split4(bv0, h, l); *(float4*)&Bh[kB0][nqB0] = h; *(float4*)&Bl[kB0][nqB0] = l;
        split4(bv1, h, l); *(float4*)&Bh[kB1][nqB1] = h; *(float4*)&Bl[kB1][nqB1] = l;
        __syncthreads();

        // prefetch next tile (hidden under MMA)
        if (k0 + 16 < DM_) {
            av0 = *(const float4*)(pA0 + k0 + 16);
            av1 = *(const float4*)(pA1 + k0 + 16);
            bv0 = *(const float4*)(pB0 + (size_t)(k0 + 16) * D_);
            bv1 = *(const float4*)(pB1 + (size_t)(k0 + 16) * D_);
        }

#pragma unroll
        for (int ks = 0; ks < 2; ks++) {
            const int kb = ks * 8;
            unsigned bhf[4][2], blf[4][2];
#pragma unroll
            for (int nt = 0; nt < 4; nt++) {
                int cn = wn0 + nt * 8 + r;
                bhf[nt][0] = __float_as_uint(Bh[kb + c][cn]);
                bhf[nt][1] = __float_as_uint(Bh[kb + c + 4][cn]);
                blf[nt][0] = __float_as_uint(Bl[kb + c][cn]);
                blf[nt][1] = __float_as_uint(Bl[kb + c + 4][cn]);
            }
#pragma unroll
            for (int mt = 0; mt < 4; mt++) {
                int row = wm0 + mt * 16 + r;
                unsigned ahf[4], alf[4];
                ahf[0] = __float_as_uint(Ah[row][kb + c]);
                ahf[1] = __float_as_uint(Ah[row + 8][kb + c]);
                ahf[2] = __float_as_uint(Ah[row][kb + c + 4]);
                ahf[3] = __float_as_uint(Ah[row + 8][kb + c + 4]);
                alf[0] = __float_as_uint(Al[row][kb + c]);
                alf[1] = __float_as_uint(Al[row + 8][kb + c]);
                alf[2] = __float_as_uint(Al[row][kb + c + 4]);
                alf[3] = __float_as_uint(Al[row + 8][kb + c + 4]);
#pragma unroll
                for (int nt = 0; nt < 4; nt++) {
                    mma_tf32(cacc[mt][nt], ahf, blf[nt]);
                    mma_tf32(cacc[mt][nt], alf, bhf[nt]);
                    mma_tf32(cacc[mt][nt], ahf, bhf[nt]);
                }
            }
        }
        __syncthreads();
    }

    // epilogue: bias + transposed store
    const int b = m0 >> LOG2L;
    const int tbase = (m0 & (L_ - 1)) + wm0 + r;
#pragma unroll
    for (int nt = 0; nt < 4; nt++) {
        const int d0 = n0 + wn0 + nt * 8 + 2 * c;
        const float bi0 = bias[d0];
        const float bi1 = bias[d0 + 1];
        const size_t row0 = ((size_t)(b * D_ + d0) << LOG2L);
        const size_t row1 = row0 + L_;
#pragma unroll
        for (int mt = 0; mt < 4; mt++) {
            const int t = tbase + mt * 16;
            outT[row0 + t]     = cacc[mt][nt][0] + bi0;
            outT[row1 + t]     = cacc[mt][nt][1] + bi1;
            outT[row0 + t + 8] = cacc[mt][nt][2] + bi0;
            outT[row1 + t + 8] = cacc[mt][nt][3] + bi1;
        }
    }
}

// ---------------- complex helpers ----------------
__device__ __forceinline__ float2 cmul(float2 a, float2 b) {
    return make_float2(a.x * b.x - a.y * b.y, a.x * b.y + a.y * b.x);
}
__device__ __forceinline__ float2 cmulc(float2 a, float2 b) {   // a * conj(b)
    return make_float2(a.x * b.x + a.y * b.y, a.y * b.x - a.x * b.y);
}

// ---------------- fused FFT-correlation + top-k + softmax + gather ----------------
// One CTA per (b, d). 256 threads; each holds 8 points at stride 256.
// Stages with span>=256 are register-resident (pairs live in one thread).
__global__ __launch_bounds__(256)
void corr_attn_kernel() {
    __shared__ float2 tw[L_ / 2];     // 8 KB
    __shared__ float2 z[L_];          // 16 KB (later reused as v column)
    __shared__ float2 s[L_];          // 16 KB
    __shared__ float  red_v[16];
    __shared__ int    red_i[16];

    const int tid = threadIdx.x;
    const int lane = tid & 31;
    const int warp = tid >> 5;
    const int bd = blockIdx.x;
    const size_t col = (size_t)bd << LOG2L;

    for (int i = tid; i < L_ / 2; i += 256) tw[i] = g_tw[i];

    // load q,k straight into registers: zr[q] holds point tid + 256q
    float2 zr[8];
#pragma unroll
    for (int q = 0; q < 8; q++)
        zr[q] = make_float2(g_qT[col + tid + 256 * q], g_kT[col + tid + 256 * q]);
    __syncthreads();   // twiddles ready

    // ---- forward DIF, register stages: span 1024, 512, 256 ----
#pragma unroll
    for (int q = 0; q < 4; q++) {        // span 1024
        float2 a = zr[q], b = zr[q + 4];
        float2 wv = tw[tid + 256 * q];
        zr[q] = make_float2(a.x + b.x, a.y + b.y);
        zr[q + 4] = cmul(make_float2(a.x - b.x, a.y - b.y), wv);
    }
#pragma unroll
    for (int g = 0; g < 8; g += 4)       // span 512
#pragma unroll
        for (int q = 0; q < 2; q++) {
            float2 a = zr[g + q], b = zr[g + q + 2];
            float2 wv = tw[(tid + 256 * q) << 1];
            zr[g + q] = make_float2(a.x + b.x, a.y + b.y);
            zr[g + q + 2] = cmul(make_float2(a.x - b.x, a.y - b.y), wv);
        }
    {
        float2 wv = tw[tid << 2];        // span 256 (same twiddle for all 4 pairs)
#pragma unroll
        for (int p = 0; p < 8; p += 2) {
            float2 a = zr[p], b = zr[p + 1];
            zr[p] = make_float2(a.x + b.x, a.y + b.y);
            zr[p + 1] = cmul(make_float2(a.x - b.x, a.y - b.y), wv);
        }
    }
#pragma unroll
    for (int q = 0; q < 8; q++) z[tid + 256 * q] = zr[q];
    __syncthreads();

    // ---- forward DIF, smem stages: span 128..1 ----
#pragma unroll 1
    for (int ls = 7; ls >= 0; ls--) {
        const int span = 1 << ls;
#pragma unroll
        for (int rr = 0; rr < 4; rr++) {
            int bf = tid + rr * 256;
            int j = bf & (span - 1);
            int g = bf >> ls;
            int i0 = (g << (ls + 1)) | j;
            int i1 = i0 + span;
            float2 a = z[i0], b = z[i1];
            float2 wv = tw[j << (10 - ls)];
            z[i0] = make_float2(a.x + b.x, a.y + b.y);
            z[i1] = cmul(make_float2(a.x - b.x, a.y - b.y), wv);
        }
        __syncthreads();
    }

    // ---- cross-spectrum in bit-reversed domain ----
    const float scl = 0.25f / (float)L_;
    for (int p = tid; p < L_; p += 256) {
        int f = __brev((unsigned)p) >> 21;
        int fm = (L_ - f) & (L_ - 1);
        int pm = __brev((unsigned)fm) >> 21;
        float2 Zf = z[p], Zm = z[pm];
        float2 u = make_float2(Zf.x + Zm.x, Zf.y - Zm.y);
        float2 v = make_float2(Zf.x - Zm.x, -Zf.y - Zm.y);
        float2 pr = cmul(u, v);
        s[p] = make_float2(-pr.y * scl, pr.x * scl);
    }
    __syncthreads();

    // hoist v-column load (z is free now); completes under inverse FFT
    float* vcol = (float*)z;
    for (int i = tid; i < L_; i += 256) vcol[i] = g_vT[col + i];

    // ---- inverse DIT, smem stages: span 1..128 ----
#pragma unroll 1
    for (int ls = 0; ls <= 7; ls++) {
        const int span = 1 << ls;
#pragma unroll
        for (int rr = 0; rr < 4; rr++) {
            int bf = tid + rr * 256;
            int j = bf & (span - 1);
            int g = bf >> ls;
            int i0 = (g << (ls + 1)) | j;
            int i1 = i0 + span;
            float2 wv = tw[j << (10 - ls)];
            float2 bwv = cmulc(s[i1], wv);
            float2 a = s[i0];
            s[i0] = make_float2(a.x + bwv.x, a.y + bwv.y);
            s[i1] = make_float2(a.x - bwv.x, a.y - bwv.y);
        }
        __syncthreads();
    }

    // ---- inverse DIT, register stages: span 256, 512, 1024 ----
    float2 sr[8];
#pragma unroll
    for (int q = 0; q < 8; q++) sr[q] = s[tid + 256 * q];
    {
        float2 wv = tw[tid << 2];        // span 256
#pragma unroll
        for (int p = 0; p < 8; p += 2) {
            float2 bwv = cmulc(sr[p + 1], wv);
            float2 a = sr[p];
            sr[p] = make_float2(a.x + bwv.x, a.y + bwv.y);
            sr[p + 1] = make_float2(a.x - bwv.x, a.y - bwv.y);
        }
    }
#pragma unroll
    for (int g = 0; g < 8; g += 4)       // span 512
#pragma unroll
        for (int q = 0; q < 2; q++) {
            float2 wv = tw[(tid + 256 * q) << 1];
            float2 bwv = cmulc(sr[g + q + 2], wv);
            float2 a = sr[g + q];
            sr[g + q] = make_float2(a.x + bwv.x, a.y + bwv.y);
            sr[g + q + 2] = make_float2(a.x - bwv.x, a.y - bwv.y);
        }
#pragma unroll
    for (int q = 0; q < 4; q++) {        // span 1024
        float2 wv = tw[tid + 256 * q];
        float2 bwv = cmulc(sr[q + 4], wv);
        float2 a = sr[q];
        sr[q] = make_float2(a.x + bwv.x, a.y + bwv.y);
        sr[q + 4] = make_float2(a.x - bwv.x, a.y - bwv.y);
    }
    // sr[q].x = R[tid + 256q]

    // ---- top-15: register values + warp shuffle + cross-warp reduce ----
    float rv[8];
#pragma unroll
    for (int q = 0; q < 8; q++) rv[q] = sr[q].x;

    float wsel[KTOP];
    int isel[KTOP];
#pragma unroll 1
    for (int rnd = 0; rnd < KTOP; rnd++) {
        float best = rv[0];
        int bq = 0;
#pragma unroll
        for (int q = 1; q < 8; q++)
            if (rv[q] > best) { best = rv[q]; bq = q; }
        int bi = tid + bq * 256;
#pragma unroll
        for (int off = 16; off > 0; off >>= 1) {
            float ov = __shfl_xor_sync(0xffffffffu, best, off);
            int oi = __shfl_xor_sync(0xffffffffu, bi, off);
            if (ov > best || (ov == best && oi < bi)) { best = ov; bi = oi; }
        }
        const int slot = (rnd & 1) * 8;
        if (lane == 0) { red_v[slot + warp] = best; red_i[slot + warp] = bi; }
        __syncthreads();
        float gb = red_v[slot];
        int gi = red_i[slot];
#pragma unroll
        for (int ww = 1; ww < 8; ww++) {
            float ov = red_v[slot + ww];
            int oi = red_i[slot + ww];
            if (ov > gb || (ov == gb && oi < gi)) { gb = ov; gi = oi; }
        }
        wsel[rnd] = gb;
        isel[rnd] = gi;
        if ((gi & 255) == tid) rv[gi >> 8] = -FLT_MAX;
    }

    // ---- softmax over the 15 selected (redundant per thread) ----
    float m = wsel[0];
#pragma unroll
    for (int k = 1; k < KTOP; k++) m = fmaxf(m, wsel[k]);
    float sum = 0.0f;
    float wnorm[KTOP];
#pragma unroll
    for (int k = 0; k < KTOP; k++) { float e = __expf(wsel[k] - m); wnorm[k] = e; sum += e; }
    const float inv = 1.0f / sum;
#pragma unroll
    for (int k = 0; k < KTOP; k++) wnorm[k] *= inv;

    // ---- gather: A^T[b,d,l] = sum_k w[k] * v[(l + lag_k) mod L] ----
    // (vcol writes are ordered before the inverse-stage __syncthreads barriers)
    for (int l = tid; l < L_; l += 256) {
        float acc = 0.0f;
#pragma unroll
        for (int k = 0; k < KTOP; k++)
            acc = fmaf(wnorm[k], vcol[(l + isel[k]) & (L_ - 1)], acc);
        g_AT[col + l] = acc;
    }
}

// ---------------- transpose (B, D, L) -> (B, L, D) ----------------
__global__ void transpose_kernel(float* __restrict__ A) {
    __shared__ float tile[32][33];
    const int b = blockIdx.z;
    const int l0 = blockIdx.x * 32;
    const int d0 = blockIdx.y * 32;
    const int tx = threadIdx.x, ty = threadIdx.y;
#pragma unroll
    for (int r = 0; r < 32; r += 8)
        tile[ty + r][tx] = g_AT[((size_t)(b * D_ + d0 + ty + r) << LOG2L) + l0 + tx];
    __syncthreads();
#pragma unroll
    for (int r = 0; r < 32; r += 8)
        A[((size_t)(b * L_ + l0 + ty + r)) * D_ + d0 + tx] = tile[tx][ty + r];
}

// ---------------- launch ----------------
extern "C" void kernel_launch(void* const* d_in, const int* in_sizes, int n_in,
                              void* d_out, int out_size) {
    const float* Q   = (const float*)d_in[0];
    const float* K   = (const float*)d_in[1];
    const float* V   = (const float*)d_in[2];
    const float* WQw = (const float*)d_in[3];
    const float* WQb = (const float*)d_in[4];
    const float* WKw = (const float*)d_in[5];
    const float* WKb = (const float*)d_in[6];
    const float* WVw = (const float*)d_in[7];
    const float* WVb = (const float*)d_in[8];
    float* out = (float*)d_out;

    twiddle_init_kernel<<<4, 256>>>();

    dim3 ggrid(B_ * L_ / 128, D_ / 128, 3);   // (128, 4, 3)
    gemm3_tf32_kernel<<<ggrid, 256>>>(Q, K, V, WQw, WKw, WVw, WQb, WKb, WVb);

    corr_attn_kernel<<<B_ * D_, 256>>>();

    dim3 tgrid(L_ / 32, D_ / 32, B_);         // (64, 16, 8)
    transpose_kernel<<<tgrid, dim3(32, 8)>>>(out);
}

// round 5
// speedup vs baseline: 2.0086x; 1.5116x over previous
#include <cuda_runtime.h>
#include <cuda_fp16.h>
#include <math.h>
#include <float.h>

// Problem constants
#define B_   8
#define L_   2048
#define LOG2L 11
#define D_   512
#define DM_  512
#define KTOP 15

// ---------------- device scratch (static allocation only) ----------------
__device__ float g_qT[B_ * D_ * L_];   // (B, D, L)
__device__ float g_kT[B_ * D_ * L_];
__device__ float g_vT[B_ * D_ * L_];
__device__ float g_AT[B_ * D_ * L_];
__device__ float2 g_tw[L_ / 2];        // exp(-2*pi*i*j/L)

// ---------------- twiddle init ----------------
__global__ void twiddle_init_kernel() {
    int j = blockIdx.x * blockDim.x + threadIdx.x;
    if (j < L_ / 2) {
        float sn, cs;
        sincospif((float)j / 1024.0f, &sn, &cs);
        g_tw[j] = make_float2(cs, -sn);
    }
}

// ---------------- FP16 split helpers ----------------
__device__ __forceinline__ unsigned pack_hi(float a, float b) {
    __half2 h = __halves2half2(__float2half_rn(a), __float2half_rn(b));
    return *(unsigned*)&h;
}
__device__ __forceinline__ unsigned pack_lo(float a, float b) {
    float ra = a - __half2float(__float2half_rn(a));
    float rb = b - __half2float(__float2half_rn(b));
    __half2 h = __halves2half2(__float2half_rn(ra), __float2half_rn(rb));
    return *(unsigned*)&h;
}

__device__ __forceinline__ void mma_f16(float c[4], const unsigned a[4], const unsigned b[2]) {
    asm volatile(
        "mma.sync.aligned.m16n8k16.row.col.f32.f16.f16.f32 "
        "{%0,%1,%2,%3}, {%4,%5,%6,%7}, {%8,%9}, {%0,%1,%2,%3};\n"
        : "+f"(c[0]), "+f"(c[1]), "+f"(c[2]), "+f"(c[3])
        : "r"(a[0]), "r"(a[1]), "r"(a[2]), "r"(a[3]), "r"(b[0]), "r"(b[1]));
}

// ---------------- Fused 3-GEMM (fp16 split x3 products, fp32 accum) ----------------
// out^T[b,d,t] = X @ W + bias. CTA tile 128(t) x 128(d), K-tile 16.
// 8 warps as 2(m) x 4(n); warp tile 64x32; mma m16n8k16.
__global__ __launch_bounds__(256, 2)
void gemm3_fp16_kernel(const float* __restrict__ Qi, const float* __restrict__ Ki,
                       const float* __restrict__ Vi,
                       const float* __restrict__ WQ, const float* __restrict__ WK,
                       const float* __restrict__ WV,
                       const float* __restrict__ bQ, const float* __restrict__ bK,
                       const float* __restrict__ bV) {
    const int z = blockIdx.z;
    const float* X    = (z == 0) ? Qi : ((z == 1) ? Ki : Vi);
    const float* W    = (z == 0) ? WQ : ((z == 1) ? WK : WV);
    const float* bias = (z == 0) ? bQ : ((z == 1) ? bK : bV);
    float* outT       = (z == 0) ? g_qT : ((z == 1) ? g_kT : g_vT);

    // half2-packed tiles: As2[row][kpair] (kpair = k/2, 8 + 1 pad), Bs2[kpair][n] (+4 pad)
    __shared__ unsigned As2h[128][9], As2l[128][9];
    __shared__ unsigned Bs2h[8][132], Bs2l[8][132];

    const int tid = threadIdx.x;
    const int lane = tid & 31;
    const int w = tid >> 5;
    const int wm0 = (w & 1) * 64;
    const int wn0 = (w >> 1) * 32;
    const int g = lane >> 2;    // 0..7
    const int c = lane & 3;     // 0..3
    const int m0 = blockIdx.x * 128;
    const int n0 = blockIdx.y * 128;

    // global load mapping
    const int rowA = tid >> 2;             // 0..63 (and +64)
    const int kqA  = (tid & 3) << 2;       // 0,4,8,12
    const int pB   = tid >> 5;             // 0..7 (kpair)
    const int nqB  = (lane) << 2;          // 0..124
    const float* pA0 = &X[(size_t)(m0 + rowA) * DM_ + kqA];
    const float* pA1 = pA0 + (size_t)64 * DM_;
    const float* pB0 = &W[(size_t)(2 * pB) * D_ + n0 + nqB];
    const float* pB1 = pB0 + D_;

    float cacc[4][4][4];
#pragma unroll
    for (int mt = 0; mt < 4; mt++)
#pragma unroll
        for (int nt = 0; nt < 4; nt++)
#pragma unroll
            for (int i = 0; i < 4; i++) cacc[mt][nt][i] = 0.0f;

    float4 av0 = *(const float4*)pA0;
    float4 av1 = *(const float4*)pA1;
    float4 bv0 = *(const float4*)pB0;
    float4 bv1 = *(const float4*)pB1;

#pragma unroll 1
    for (int k0 = 0; k0 < DM_; k0 += 16) {
        // pack current tile into half2 hi/lo
        const int kp = kqA >> 1;
        As2h[rowA][kp]          = pack_hi(av0.x, av0.y);
        As2h[rowA][kp + 1]      = pack_hi(av0.z, av0.w);
        As2l[rowA][kp]          = pack_lo(av0.x, av0.y);
        As2l[rowA][kp + 1]      = pack_lo(av0.z, av0.w);
        As2h[rowA + 64][kp]     = pack_hi(av1.x, av1.y);
        As2h[rowA + 64][kp + 1] = pack_hi(av1.z, av1.w);
        As2l[rowA + 64][kp]     = pack_lo(av1.x, av1.y);
        As2l[rowA + 64][kp + 1] = pack_lo(av1.z, av1.w);
        {
            uint4 uh = make_uint4(pack_hi(bv0.x, bv1.x), pack_hi(bv0.y, bv1.y),
                                  pack_hi(bv0.z, bv1.z), pack_hi(bv0.w, bv1.w));
            uint4 ul = make_uint4(pack_lo(bv0.x, bv1.x), pack_lo(bv0.y, bv1.y),
                                  pack_lo(bv0.z, bv1.z), pack_lo(bv0.w, bv1.w));
            *(uint4*)&Bs2h[pB][nqB] = uh;
            *(uint4*)&Bs2l[pB][nqB] = ul;
        }
        __syncthreads();

        // prefetch next k-tile
        if (k0 + 16 < DM_) {
            av0 = *(const float4*)(pA0 + k0 + 16);
            av1 = *(const float4*)(pA1 + k0 + 16);
            bv0 = *(const float4*)(pB0 + (size_t)(k0 + 16) * D_);
            bv1 = *(const float4*)(pB1 + (size_t)(k0 + 16) * D_);
        }

        // fragments + MMA (k-step = full 16)
        unsigned bh[4][2], bl[4][2];
#pragma unroll
        for (int nt = 0; nt < 4; nt++) {
            int cn = wn0 + nt * 8 + g;
            bh[nt][0] = Bs2h[c][cn];
            bh[nt][1] = Bs2h[c + 4][cn];
            bl[nt][0] = Bs2l[c][cn];
            bl[nt][1] = Bs2l[c + 4][cn];
        }
#pragma unroll
        for (int mt = 0; mt < 4; mt++) {
            int row = wm0 + mt * 16 + g;
            unsigned ah[4], al[4];
            ah[0] = As2h[row][c];
            ah[1] = As2h[row + 8][c];
            ah[2] = As2h[row][c + 4];
            ah[3] = As2h[row + 8][c + 4];
            al[0] = As2l[row][c];
            al[1] = As2l[row + 8][c];
            al[2] = As2l[row][c + 4];
            al[3] = As2l[row + 8][c + 4];
#pragma unroll
            for (int nt = 0; nt < 4; nt++) {
                mma_f16(cacc[mt][nt], ah, bl[nt]);
                mma_f16(cacc[mt][nt], al, bh[nt]);
                mma_f16(cacc[mt][nt], ah, bh[nt]);
            }
        }
        __syncthreads();
    }

    // epilogue: bias + transposed store
    const int b = m0 >> LOG2L;
    const int tbase = (m0 & (L_ - 1)) + wm0 + g;
#pragma unroll
    for (int nt = 0; nt < 4; nt++) {
        const int d0 = n0 + wn0 + nt * 8 + 2 * c;
        const float bi0 = bias[d0];
        const float bi1 = bias[d0 + 1];
        const size_t row0 = ((size_t)(b * D_ + d0) << LOG2L);
        const size_t row1 = row0 + L_;
#pragma unroll
        for (int mt = 0; mt < 4; mt++) {
            const int t = tbase + mt * 16;
            outT[row0 + t]     = cacc[mt][nt][0] + bi0;
            outT[row1 + t]     = cacc[mt][nt][1] + bi1;
            outT[row0 + t + 8] = cacc[mt][nt][2] + bi0;
            outT[row1 + t + 8] = cacc[mt][nt][3] + bi1;
        }
    }
}

// ---------------- complex helpers ----------------
__device__ __forceinline__ float2 cmul(float2 a, float2 b) {
    return make_float2(a.x * b.x - a.y * b.y, a.x * b.y + a.y * b.x);
}
__device__ __forceinline__ float2 cmulc(float2 a, float2 b) {   // a * conj(b)
    return make_float2(a.x * b.x + a.y * b.y, a.y * b.x - a.x * b.y);
}
__device__ __forceinline__ float2 cadd(float2 a, float2 b) { return make_float2(a.x + b.x, a.y + b.y); }
__device__ __forceinline__ float2 csub(float2 a, float2 b) { return make_float2(a.x - b.x, a.y - b.y); }

// padded smem index (reduces bank conflicts for strided exchanges)
#define ZI(i) ((i) + ((i) >> 5))

// ---------------- fused FFT-correlation + top-k + softmax + gather ----------------
// One CTA per (b, d). 256 threads; 8 points/thread. All butterflies in registers;
// 3 smem exchanges per direction (stride 256 -> 32 -> 4 -> 1 ownership).
__global__ __launch_bounds__(256)
void corr_attn_kernel() {
    __shared__ float2 tw[L_ / 2];          // 8 KB
    __shared__ float2 z[L_ + L_ / 32];     // 16.5 KB (reused as v column)
    __shared__ float2 s[L_ + L_ / 32];     // 16.5 KB
    __shared__ float  red_v[16];
    __shared__ int    red_i[16];

    const int tid = threadIdx.x;
    const int lane = tid & 31;
    const int warp = tid >> 5;
    const int bd = blockIdx.x;
    const size_t col = (size_t)bd << LOG2L;

    const int l32 = lane;                       // c32 = l + (tid>>5)*256
    const int c32 = l32 + (tid >> 5) * 256;
    const int t1 = tid & 3;
    const int c4 = t1 + (tid >> 2) * 32;

    for (int i = tid; i < L_ / 2; i += 256) tw[i] = g_tw[i];

    float2 zr[8];
#pragma unroll
    for (int q = 0; q < 8; q++)
        zr[q] = make_float2(g_qT[col + tid + 256 * q], g_kT[col + tid + 256 * q]);
    __syncthreads();   // twiddles ready

    // ======== forward DIF ========
    // group 1: stride-256 ownership, spans 1024/512/256
#pragma unroll
    for (int q = 0; q < 4; q++) {
        float2 a = zr[q], b = zr[q + 4];
        float2 wv = tw[tid + 256 * q];
        zr[q] = cadd(a, b);
        zr[q + 4] = cmul(csub(a, b), wv);
    }
#pragma unroll
    for (int gg = 0; gg < 8; gg += 4)
#pragma unroll
        for (int q = 0; q < 2; q++) {
            float2 a = zr[gg + q], b = zr[gg + q + 2];
            float2 wv = tw[(tid + 256 * q) << 1];
            zr[gg + q] = cadd(a, b);
            zr[gg + q + 2] = cmul(csub(a, b), wv);
        }
    {
        float2 wv = tw[tid << 2];
#pragma unroll
        for (int p = 0; p < 8; p += 2) {
            float2 a = zr[p], b = zr[p + 1];
            zr[p] = cadd(a, b);
            zr[p + 1] = cmul(csub(a, b), wv);
        }
    }
#pragma unroll
    for (int q = 0; q < 8; q++) z[ZI(tid + 256 * q)] = zr[q];
    __syncthreads();

    // group 2: stride-32 ownership, spans 128/64/32
#pragma unroll
    for (int q = 0; q < 8; q++) zr[q] = z[ZI(c32 + 32 * q)];
#pragma unroll
    for (int q = 0; q < 4; q++) {
        float2 a = zr[q], b = zr[q + 4];
        float2 wv = tw[(l32 + 32 * q) << 3];
        zr[q] = cadd(a, b);
        zr[q + 4] = cmul(csub(a, b), wv);
    }
#pragma unroll
    for (int gg = 0; gg < 8; gg += 4)
#pragma unroll
        for (int q = 0; q < 2; q++) {
            float2 a = zr[gg + q], b = zr[gg + q + 2];
            float2 wv = tw[(l32 + 32 * q) << 4];
            zr[gg + q] = cadd(a, b);
            zr[gg + q + 2] = cmul(csub(a, b), wv);
        }
    {
        float2 wv = tw[l32 << 5];
#pragma unroll
        for (int p = 0; p < 8; p += 2) {
            float2 a = zr[p], b = zr[p + 1];
            zr[p] = cadd(a, b);
            zr[p + 1] = cmul(csub(a, b), wv);
        }
    }
#pragma unroll
    for (int q = 0; q < 8; q++) z[ZI(c32 + 32 * q)] = zr[q];
    __syncthreads();

    // group 3: stride-4 ownership, spans 16/8/4
#pragma unroll
    for (int q = 0; q < 8; q++) zr[q] = z[ZI(c4 + 4 * q)];
#pragma unroll
    for (int q = 0; q < 4; q++) {
        float2 a = zr[q], b = zr[q + 4];
        float2 wv = tw[(t1 + 4 * q) << 6];
        zr[q] = cadd(a, b);
        zr[q + 4] = cmul(csub(a, b), wv);
    }
#pragma unroll
    for (int gg = 0; gg < 8; gg += 4)
#pragma unroll
        for (int q = 0; q < 2; q++) {
            float2 a = zr[gg + q], b = zr[gg + q + 2];
            float2 wv = tw[(t1 + 4 * q) << 7];
            zr[gg + q] = cadd(a, b);
            zr[gg + q + 2] = cmul(csub(a, b), wv);
        }
    {
        float2 wv = tw[t1 << 8];
#pragma unroll
        for (int p = 0; p < 8; p += 2) {
            float2 a = zr[p], b = zr[p + 1];
            zr[p] = cadd(a, b);
            zr[p + 1] = cmul(csub(a, b), wv);
        }
    }
#pragma unroll
    for (int q = 0; q < 8; q++) z[ZI(c4 + 4 * q)] = zr[q];
    __syncthreads();

    // group 4: contiguous ownership, spans 2/1
    const int base8 = tid * 8;
#pragma unroll
    for (int q = 0; q < 8; q++) zr[q] = z[ZI(base8 + q)];
#pragma unroll
    for (int gg = 0; gg < 8; gg += 4)
#pragma unroll
        for (int q = 0; q < 2; q++) {
            float2 a = zr[gg + q], b = zr[gg + q + 2];
            float2 wv = tw[(q & 1) << 9];
            zr[gg + q] = cadd(a, b);
            zr[gg + q + 2] = cmul(csub(a, b), wv);
        }
#pragma unroll
    for (int p = 0; p < 8; p += 2) {
        float2 a = zr[p], b = zr[p + 1];
        zr[p] = cadd(a, b);
        zr[p + 1] = csub(a, b);
    }
#pragma unroll
    for (int q = 0; q < 8; q++) z[ZI(base8 + q)] = zr[q];
    __syncthreads();

    // ======== cross-spectrum in bit-reversed domain ========
    const float scl = 0.25f / (float)L_;
    for (int p = tid; p < L_; p += 256) {
        int f = __brev((unsigned)p) >> 21;
        int fm = (L_ - f) & (L_ - 1);
        int pm = __brev((unsigned)fm) >> 21;
        float2 Zf = z[ZI(p)], Zm = z[ZI(pm)];
        float2 u = make_float2(Zf.x + Zm.x, Zf.y - Zm.y);
        float2 v = make_float2(Zf.x - Zm.x, -Zf.y - Zm.y);
        float2 pr = cmul(u, v);
        s[ZI(p)] = make_float2(-pr.y * scl, pr.x * scl);
    }
    __syncthreads();

    // hoist v-column load (z free now); completes under inverse FFT
    float* vcol = (float*)z;
    for (int i = tid; i < L_; i += 256) vcol[i] = g_vT[col + i];

    // ======== inverse DIT ========
    float2 sr[8];
    // group 4': contiguous, spans 1/2
#pragma unroll
    for (int q = 0; q < 8; q++) sr[q] = s[ZI(base8 + q)];
#pragma unroll
    for (int p = 0; p < 8; p += 2) {
        float2 a = sr[p], b = sr[p + 1];
        sr[p] = cadd(a, b);
        sr[p + 1] = csub(a, b);
    }
#pragma unroll
    for (int gg = 0; gg < 8; gg += 4)
#pragma unroll
        for (int q = 0; q < 2; q++) {
            float2 wv = tw[(q & 1) << 9];
            float2 bw = cmulc(sr[gg + q + 2], wv);
            float2 a = sr[gg + q];
            sr[gg + q] = cadd(a, bw);
            sr[gg + q + 2] = csub(a, bw);
        }
#pragma unroll
    for (int q = 0; q < 8; q++) s[ZI(base8 + q)] = sr[q];
    __syncthreads();

    // group 3': stride-4, spans 4/8/16
#pragma unroll
    for (int q = 0; q < 8; q++) sr[q] = s[ZI(c4 + 4 * q)];
    {
        float2 wv = tw[t1 << 8];
#pragma unroll
        for (int p = 0; p < 8; p += 2) {
            float2 bw = cmulc(sr[p + 1], wv);
            float2 a = sr[p];
            sr[p] = cadd(a, bw);
            sr[p + 1] = csub(a, bw);
        }
    }
#pragma unroll
    for (int gg = 0; gg < 8; gg += 4)
#pragma unroll
        for (int q = 0; q < 2; q++) {
            float2 wv = tw[(t1 + 4 * q) << 7];
            float2 bw = cmulc(sr[gg + q + 2], wv);
            float2 a = sr[gg + q];
            sr[gg + q] = cadd(a, bw);
            sr[gg + q + 2] = csub(a, bw);
        }
#pragma unroll
    for (int q = 0; q < 4; q++) {
        float2 wv = tw[(t1 + 4 * q) << 6];
        float2 bw = cmulc(sr[q + 4], wv);
        float2 a = sr[q];
        sr[q] = cadd(a, bw);
        sr[q + 4] = csub(a, bw);
    }
#pragma unroll
    for (int q = 0; q < 8; q++) s[ZI(c4 + 4 * q)] = sr[q];
    __syncthreads();

    // group 2': stride-32, spans 32/64/128
#pragma unroll
    for (int q = 0; q < 8; q++) sr[q] = s[ZI(c32 + 32 * q)];
    {
        float2 wv = tw[l32 << 5];
#pragma unroll
        for (int p = 0; p < 8; p += 2) {
            float2 bw = cmulc(sr[p + 1], wv);
            float2 a = sr[p];
            sr[p] = cadd(a, bw);
            sr[p + 1] = csub(a, bw);
        }
    }
#pragma unroll
    for (int gg = 0; gg < 8; gg += 4)
#pragma unroll
        for (int q = 0; q < 2; q++) {
            float2 wv = tw[(l32 + 32 * q) << 4];
            float2 bw = cmulc(sr[gg + q + 2], wv);
            float2 a = sr[gg + q];
            sr[gg + q] = cadd(a, bw);
            sr[gg + q + 2] = csub(a, bw);
        }
#pragma unroll
    for (int q = 0; q < 4; q++) {
        float2 wv = tw[(l32 + 32 * q) << 3];
        float2 bw = cmulc(sr[q + 4], wv);
        float2 a = sr[q];
        sr[q] = cadd(a, bw);
        sr[q + 4] = csub(a, bw);
    }
#pragma unroll
    for (int q = 0; q < 8; q++) s[ZI(c32 + 32 * q)] = sr[q];
    __syncthreads();

    // group 1': stride-256, spans 256/512/1024 (registers; feeds top-k directly)
#pragma unroll
    for (int q = 0; q < 8; q++) sr[q] = s[ZI(tid + 256 * q)];
    {
        float2 wv = tw[tid << 2];
#pragma unroll
        for (int p = 0; p < 8; p += 2) {
            float2 bw = cmulc(sr[p + 1], wv);
            float2 a = sr[p];
            sr[p] = cadd(a, bw);
            sr[p + 1] = csub(a, bw);
        }
    }
#pragma unroll
    for (int gg = 0; gg < 8; gg += 4)
#pragma unroll
        for (int q = 0; q < 2; q++) {
            float2 wv = tw[(tid + 256 * q) << 1];
            float2 bw = cmulc(sr[gg + q + 2], wv);
            float2 a = sr[gg + q];
            sr[gg + q] = cadd(a, bw);
            sr[gg + q + 2] = csub(a, bw);
        }
#pragma unroll
    for (int q = 0; q < 4; q++) {
        float2 wv = tw[tid + 256 * q];
        float2 bw = cmulc(sr[q + 4], wv);
        float2 a = sr[q];
        sr[q] = cadd(a, bw);
        sr[q + 4] = csub(a, bw);
    }
    // sr[q].x = R[tid + 256q]

    // ---- top-15: register values + warp shuffle + cross-warp reduce ----
    float rv[8];
#pragma unroll
    for (int q = 0; q < 8; q++) rv[q] = sr[q].x;

    float wsel[KTOP];
    int isel[KTOP];
#pragma unroll 1
    for (int rnd = 0; rnd < KTOP; rnd++) {
        float best = rv[0];
        int bq = 0;
#pragma unroll
        for (int q = 1; q < 8; q++)
            if (rv[q] > best) { best = rv[q]; bq = q; }
        int bi = tid + bq * 256;
#pragma unroll
        for (int off = 16; off > 0; off >>= 1) {
            float ov = __shfl_xor_sync(0xffffffffu, best, off);
            int oi = __shfl_xor_sync(0xffffffffu, bi, off);
            if (ov > best || (ov == best && oi < bi)) { best = ov; bi = oi; }
        }
        const int slot = (rnd & 1) * 8;
        if (lane == 0) { red_v[slot + warp] = best; red_i[slot + warp] = bi; }
        __syncthreads();
        float gb = red_v[slot];
        int gi = red_i[slot];
#pragma unroll
        for (int ww = 1; ww < 8; ww++) {
            float ov = red_v[slot + ww];
            int oi = red_i[slot + ww];
            if (ov > gb || (ov == gb && oi < gi)) { gb = ov; gi = oi; }
        }
        wsel[rnd] = gb;
        isel[rnd] = gi;
        if ((gi & 255) == tid) rv[gi >> 8] = -FLT_MAX;
    }

    // ---- softmax over the 15 selected (redundant per thread) ----
    float m = wsel[0];
#pragma unroll
    for (int k = 1; k < KTOP; k++) m = fmaxf(m, wsel[k]);
    float sum = 0.0f;
    float wnorm[KTOP];
#pragma unroll
    for (int k = 0; k < KTOP; k++) { float e = __expf(wsel[k] - m); wnorm[k] = e; sum += e; }
    const float inv = 1.0f / sum;
#pragma unroll
    for (int k = 0; k < KTOP; k++) wnorm[k] *= inv;

    // ---- gather: A^T[b,d,l] = sum_k w[k] * v[(l + lag_k) mod L] ----
    for (int l = tid; l < L_; l += 256) {
        float acc = 0.0f;
#pragma unroll
        for (int k = 0; k < KTOP; k++)
            acc = fmaf(wnorm[k], vcol[(l + isel[k]) & (L_ - 1)], acc);
        g_AT[col + l] = acc;
    }
}

// ---------------- transpose (B, D, L) -> (B, L, D) ----------------
__global__ void transpose_kernel(float* __restrict__ A) {
    __shared__ float tile[32][33];
    const int b = blockIdx.z;
    const int l0 = blockIdx.x * 32;
    const int d0 = blockIdx.y * 32;
    const int tx = threadIdx.x, ty = threadIdx.y;
#pragma unroll
    for (int r = 0; r < 32; r += 8)
        tile[ty + r][tx] = g_AT[((size_t)(b * D_ + d0 + ty + r) << LOG2L) + l0 + tx];
    __syncthreads();
#pragma unroll
    for (int r = 0; r < 32; r += 8)
        A[((size_t)(b * L_ + l0 + ty + r)) * D_ + d0 + tx] = tile[tx][ty + r];
}

// ---------------- launch ----------------
extern "C" void kernel_launch(void* const* d_in, const int* in_sizes, int n_in,
                              void* d_out, int out_size) {
    const float* Q   = (const float*)d_in[0];
    const float* K   = (const float*)d_in[1];
    const float* V   = (const float*)d_in[2];
    const float* WQw = (const float*)d_in[3];
    const float* WQb = (const float*)d_in[4];
    const float* WKw = (const float*)d_in[5];
    const float* WKb = (const float*)d_in[6];
    const float* WVw = (const float*)d_in[7];
    const float* WVb = (const float*)d_in[8];
    float* out = (float*)d_out;

    twiddle_init_kernel<<<4, 256>>>();

    dim3 ggrid(B_ * L_ / 128, D_ / 128, 3);   // (128, 4, 3)
    gemm3_fp16_kernel<<<ggrid, 256>>>(Q, K, V, WQw, WKw, WVw, WQb, WKb, WVb);

    corr_attn_kernel<<<B_ * D_, 256>>>();

    dim3 tgrid(L_ / 32, D_ / 32, B_);         // (64, 16, 8)
    transpose_kernel<<<tgrid, dim3(32, 8)>>>(out);
}